// round 1
// baseline (speedup 1.0000x reference)
#include <cuda_runtime.h>
#include <cuda_bf16.h>

#define BATCH 8
#define CHN   256
#define HW2   16384
#define NTILE 32        // pixel tiles per batch in kernel A (512 px each)
#define EPSLN 1e-5f

// Scratch (device globals; no allocation allowed)
__device__ float g_xpart[BATCH * NTILE * CHN];  // per-tile channel sums
__device__ float g_sa[BATCH * HW2];             // spatial attention map
__device__ float g_ca[BATCH * CHN];             // channel attention (post-LN)
__device__ float g_ssum[BATCH * CHN];           // spatial sum of seq

__device__ __forceinline__ float hsig(float v) {
    // clip((v+3)/6, 0, 1) == saturate(v/6 + 0.5)
    return __saturatef(fmaf(v, 0.16666667f, 0.5f));
}

__device__ __forceinline__ float wred(float v) {
    v += __shfl_xor_sync(0xffffffffu, v, 16);
    v += __shfl_xor_sync(0xffffffffu, v, 8);
    v += __shfl_xor_sync(0xffffffffu, v, 4);
    v += __shfl_xor_sync(0xffffffffu, v, 2);
    v += __shfl_xor_sync(0xffffffffu, v, 1);
    return v;
}

// ---------------------------------------------------------------------------
// Kernel A: one pass over x. Produces per-tile channel sums (for xmean) and
// sa[b,p] = sum_c x[b,c,p]*w1[c] + b1.
// grid (NTILE, BATCH), 256 threads. Each block: 512 pixels, all 256 channels.
// Warp w owns channels [w*32, w*32+32) -> channel sums need no atomics.
// ---------------------------------------------------------------------------
__global__ void __launch_bounds__(256) kA(const float* __restrict__ x,
                                          const float* __restrict__ w1,
                                          const float* __restrict__ b1) {
    __shared__ float sap[8][512];   // per-warp partial sa
    __shared__ float csum[256];     // per-channel tile sums

    const int tid  = threadIdx.x;
    const int wid  = tid >> 5;
    const int lane = tid & 31;
    const int tile = blockIdx.x;
    const int b    = blockIdx.y;

    const float* xb = x + ((size_t)b * CHN) * HW2 + tile * 512;

    float sacc[4][4];
#pragma unroll
    for (int j = 0; j < 4; j++)
#pragma unroll
        for (int jj = 0; jj < 4; jj++) sacc[j][jj] = 0.f;

    const int c0 = wid * 32;
#pragma unroll 4
    for (int ci = 0; ci < 32; ci++) {
        const int c = c0 + ci;
        const float w = __ldg(w1 + c);
        const float* row = xb + (size_t)c * HW2;
        float cs = 0.f;
#pragma unroll
        for (int j = 0; j < 4; j++) {
            float4 v = *(const float4*)(row + lane * 4 + j * 128);
            cs += (v.x + v.y) + (v.z + v.w);
            sacc[j][0] = fmaf(v.x, w, sacc[j][0]);
            sacc[j][1] = fmaf(v.y, w, sacc[j][1]);
            sacc[j][2] = fmaf(v.z, w, sacc[j][2]);
            sacc[j][3] = fmaf(v.w, w, sacc[j][3]);
        }
        cs = wred(cs);
        if (lane == 0) csum[c] = cs;
    }

#pragma unroll
    for (int j = 0; j < 4; j++)
#pragma unroll
        for (int jj = 0; jj < 4; jj++)
            sap[wid][lane * 4 + j * 128 + jj] = sacc[j][jj];
    __syncthreads();

    const float b1v = __ldg(b1);
    const int p = tid * 2;
    float v0 = b1v, v1 = b1v;
#pragma unroll
    for (int w = 0; w < 8; w++) { v0 += sap[w][p]; v1 += sap[w][p + 1]; }
    *(float2*)(g_sa + b * HW2 + tile * 512 + p) = make_float2(v0, v1);
    g_xpart[(b * NTILE + tile) * CHN + tid] = csum[tid];
}

// ---------------------------------------------------------------------------
// Kernel B: tiny. xmean -> g -> ca -> hsig -> LayerNorm -> g_ca.
// grid (BATCH), 256 threads.
// ---------------------------------------------------------------------------
__global__ void __launch_bounds__(256) kB(const float* __restrict__ w0,
                                          const float* __restrict__ b0,
                                          const float* __restrict__ wb,
                                          const float* __restrict__ bbias,
                                          const float* __restrict__ gamma,
                                          const float* __restrict__ beta) {
    __shared__ float xm[256];
    __shared__ float gg[128];
    __shared__ float cav[256];
    __shared__ float red[16];

    const int b = blockIdx.x;
    const int tid = threadIdx.x;

    // xmean
    {
        float s = 0.f;
        const float* xp = g_xpart + b * NTILE * CHN + tid;
#pragma unroll
        for (int t = 0; t < NTILE; t++) s += xp[t * CHN];
        xm[tid] = s * (1.0f / (float)HW2);
    }
    __syncthreads();

    // g[o] = xmean . w0[o,:] + b0[o]   (o < 128)
    if (tid < 128) {
        float acc = __ldg(b0 + tid);
        const float* w = w0 + tid * 256;
#pragma unroll 8
        for (int c = 0; c < 256; c++) acc = fmaf(xm[c], __ldg(w + c), acc);
        gg[tid] = acc;
    }
    __syncthreads();

    // ca[c] = hsig(g . wb[c,:] + bb[c])
    {
        float acc = __ldg(bbias + tid);
        const float* w = wb + tid * 128;
#pragma unroll 8
        for (int o = 0; o < 128; o++) acc = fmaf(gg[o], __ldg(w + o), acc);
        cav[tid] = hsig(acc);
    }
    __syncthreads();

    // LayerNorm over the 256 channels
    const float v = cav[tid];
    float sv = v, sq = v * v;
    sv = wred(sv);
    sq = wred(sq);
    if ((tid & 31) == 0) { red[tid >> 5] = sv; red[8 + (tid >> 5)] = sq; }
    __syncthreads();
    float ts = 0.f, tq = 0.f;
#pragma unroll
    for (int i = 0; i < 8; i++) { ts += red[i]; tq += red[8 + i]; }
    const float mu  = ts * (1.0f / 256.0f);
    const float var = tq * (1.0f / 256.0f) - mu * mu;
    const float r   = rsqrtf(var + EPSLN);
    g_ca[b * CHN + tid] = (v - mu) * r * __ldg(gamma + tid) + __ldg(beta + tid);
}

// ---------------------------------------------------------------------------
// Kernel C: ssum[b,c] = sum_p hsig(ca[b,c] * sa[b,p]).
// grid (32, BATCH): block handles 8 channels x all 16384 pixels.
// ---------------------------------------------------------------------------
__global__ void __launch_bounds__(256) kC() {
    const int b   = blockIdx.y;
    const int c0  = blockIdx.x * 8;
    const int tid = threadIdx.x;
    const int wid = tid >> 5;
    const int lane = tid & 31;

    float cav[8];
#pragma unroll
    for (int i = 0; i < 8; i++) cav[i] = g_ca[b * CHN + c0 + i];

    const float* sap = g_sa + b * HW2;
    float s[8];
#pragma unroll
    for (int i = 0; i < 8; i++) s[i] = 0.f;

    for (int k = 0; k < 64; k++) {
        const float v = sap[tid + k * 256];
#pragma unroll
        for (int i = 0; i < 8; i++) s[i] += hsig(cav[i] * v);
    }

    __shared__ float red[8][8];
#pragma unroll
    for (int i = 0; i < 8; i++) {
        float t = wred(s[i]);
        if (lane == 0) red[wid][i] = t;
    }
    __syncthreads();
    if (tid < 8) {
        float t = 0.f;
#pragma unroll
        for (int w = 0; w < 8; w++) t += red[w][tid];
        g_ssum[b * CHN + c0 + tid] = t;
    }
}

// ---------------------------------------------------------------------------
// Kernel D: out[b,o,p] = hsig(ca[b,o]*sa[b,p]) + ssum[b,o]
//                        + (sum_c x[b,c,p]*wr[o,c]) + br[o]
// Tiled fp32 SGEMM 128x128, K-tile 16, 256 threads, 8x8 per thread
// (split as 2x 4-blocks in each dim for better smem bank behavior).
// grid (128 pixel-tiles, 2 o-tiles, 8 batches).
// ---------------------------------------------------------------------------
__global__ void __launch_bounds__(256) kD(const float* __restrict__ x,
                                          const float* __restrict__ wr,
                                          const float* __restrict__ br,
                                          float* __restrict__ out) {
    __shared__ float As[16][128];   // As[k][o]
    __shared__ float Bs[16][128];   // Bs[k][p]

    const int tid = threadIdx.x;
    const int bx = blockIdx.x;      // pixel tile
    const int by = blockIdx.y;      // o tile
    const int b  = blockIdx.z;

    const int ty = tid >> 4;        // 0..15
    const int tx = tid & 15;        // 0..15

    float acc[2][2][4][4];
#pragma unroll
    for (int om = 0; om < 2; om++)
#pragma unroll
        for (int pm = 0; pm < 2; pm++)
#pragma unroll
            for (int i = 0; i < 4; i++)
#pragma unroll
                for (int j = 0; j < 4; j++) acc[om][pm][i][j] = 0.f;

    // load indices
    const int ar  = tid >> 2;          // 0..63
    const int ac4 = (tid & 3) * 4;     // 0,4,8,12
    const int bkr = tid >> 4;          // 0..15
    const int bpc = (tid & 15) * 8;    // 0..120

    const float* Agbase = wr + (size_t)(by * 128 + ar) * 256 + ac4;
    const float* Bgbase = x + ((size_t)(b * CHN) + bkr) * HW2 + bx * 128 + bpc;

    for (int kt = 0; kt < 16; kt++) {
        // A tile (wr): transpose into As[k][o]
        float4 a0 = *(const float4*)(Agbase + kt * 16);
        float4 a1 = *(const float4*)(Agbase + kt * 16 + 64 * 256);
        As[ac4 + 0][ar] = a0.x; As[ac4 + 1][ar] = a0.y;
        As[ac4 + 2][ar] = a0.z; As[ac4 + 3][ar] = a0.w;
        As[ac4 + 0][ar + 64] = a1.x; As[ac4 + 1][ar + 64] = a1.y;
        As[ac4 + 2][ar + 64] = a1.z; As[ac4 + 3][ar + 64] = a1.w;
        // B tile (x)
        const float* Bg = Bgbase + (size_t)(kt * 16) * HW2;
        *(float4*)&Bs[bkr][bpc]     = *(const float4*)Bg;
        *(float4*)&Bs[bkr][bpc + 4] = *(const float4*)(Bg + 4);
        __syncthreads();

#pragma unroll
        for (int kk = 0; kk < 16; kk++) {
            float4 av0 = *(const float4*)&As[kk][ty * 4];
            float4 av1 = *(const float4*)&As[kk][64 + ty * 4];
            float4 bv0 = *(const float4*)&Bs[kk][tx * 4];
            float4 bv1 = *(const float4*)&Bs[kk][64 + tx * 4];
            const float a[2][4] = {{av0.x, av0.y, av0.z, av0.w},
                                   {av1.x, av1.y, av1.z, av1.w}};
            const float bv[2][4] = {{bv0.x, bv0.y, bv0.z, bv0.w},
                                    {bv1.x, bv1.y, bv1.z, bv1.w}};
#pragma unroll
            for (int om = 0; om < 2; om++)
#pragma unroll
                for (int i = 0; i < 4; i++)
#pragma unroll
                    for (int pm = 0; pm < 2; pm++)
#pragma unroll
                        for (int j = 0; j < 4; j++)
                            acc[om][pm][i][j] = fmaf(a[om][i], bv[pm][j], acc[om][pm][i][j]);
        }
        __syncthreads();
    }

    // epilogue
    const int obase = by * 128;
    const int pbase = bx * 128;
    const float* caB = g_ca + b * CHN;
    const float* ssB = g_ssum + b * CHN;
    const float* saB = g_sa + b * HW2;

    float sav[2][4];
#pragma unroll
    for (int pm = 0; pm < 2; pm++)
#pragma unroll
        for (int j = 0; j < 4; j++)
            sav[pm][j] = saB[pbase + pm * 64 + tx * 4 + j];

#pragma unroll
    for (int om = 0; om < 2; om++) {
#pragma unroll
        for (int i = 0; i < 4; i++) {
            const int o = obase + om * 64 + ty * 4 + i;
            const float addv = __ldg(br + o) + ssB[o];
            const float cav  = caB[o];
            float* orow = out + ((size_t)(b * CHN) + o) * HW2 + pbase;
#pragma unroll
            for (int pm = 0; pm < 2; pm++) {
                float4 o4;
                o4.x = acc[om][pm][i][0] + addv + hsig(cav * sav[pm][0]);
                o4.y = acc[om][pm][i][1] + addv + hsig(cav * sav[pm][1]);
                o4.z = acc[om][pm][i][2] + addv + hsig(cav * sav[pm][2]);
                o4.w = acc[om][pm][i][3] + addv + hsig(cav * sav[pm][3]);
                *(float4*)(orow + pm * 64 + tx * 4) = o4;
            }
        }
    }
}

// ---------------------------------------------------------------------------
extern "C" void kernel_launch(void* const* d_in, const int* in_sizes, int n_in,
                              void* d_out, int out_size) {
    const float* x     = (const float*)d_in[0];
    const float* w0    = (const float*)d_in[1];
    const float* b0    = (const float*)d_in[2];
    const float* wb    = (const float*)d_in[3];
    const float* bb    = (const float*)d_in[4];
    const float* w1    = (const float*)d_in[5];
    const float* b1    = (const float*)d_in[6];
    const float* wr    = (const float*)d_in[7];
    const float* br    = (const float*)d_in[8];
    const float* gamma = (const float*)d_in[9];
    const float* beta  = (const float*)d_in[10];
    float* out = (float*)d_out;

    kA<<<dim3(NTILE, BATCH), 256>>>(x, w1, b1);
    kB<<<BATCH, 256>>>(w0, b0, wb, bb, gamma, beta);
    kC<<<dim3(32, BATCH), 256>>>();
    kD<<<dim3(128, 2, BATCH), 256>>>(x, wr, br, out);
}

// round 2
// speedup vs baseline: 2.7826x; 2.7826x over previous
#include <cuda_runtime.h>
#include <cuda_bf16.h>
#include <cstdint>

#define BATCH 8
#define CHN   256
#define HW2   16384
#define NTILE 32
#define EPSLN 1e-5f

// Scratch (device globals; no allocation allowed)
__device__ float g_xpart[BATCH * NTILE * CHN];
__device__ float g_sa[BATCH * HW2];
__device__ float g_ca[BATCH * CHN];
__device__ float g_ssum[BATCH * CHN];
__device__ __nv_bfloat16 g_xb[(size_t)BATCH * CHN * HW2];   // bf16 copy of x
__device__ __nv_bfloat16 g_wrb[CHN * CHN];                  // bf16 copy of wr

__device__ __forceinline__ float hsig(float v) {
    return __saturatef(fmaf(v, 0.16666667f, 0.5f));
}

__device__ __forceinline__ float wred(float v) {
    v += __shfl_xor_sync(0xffffffffu, v, 16);
    v += __shfl_xor_sync(0xffffffffu, v, 8);
    v += __shfl_xor_sync(0xffffffffu, v, 4);
    v += __shfl_xor_sync(0xffffffffu, v, 2);
    v += __shfl_xor_sync(0xffffffffu, v, 1);
    return v;
}

__device__ __forceinline__ void cpasync16(uint32_t s, const void* g) {
    asm volatile("cp.async.cg.shared.global [%0], [%1], 16;" :: "r"(s), "l"(g));
}
__device__ __forceinline__ void ldsm4(uint32_t& r0, uint32_t& r1, uint32_t& r2,
                                      uint32_t& r3, uint32_t addr) {
    asm volatile("ldmatrix.sync.aligned.m8n8.x4.shared.b16 {%0,%1,%2,%3}, [%4];"
                 : "=r"(r0), "=r"(r1), "=r"(r2), "=r"(r3) : "r"(addr));
}
__device__ __forceinline__ void ldsm4t(uint32_t& r0, uint32_t& r1, uint32_t& r2,
                                       uint32_t& r3, uint32_t addr) {
    asm volatile("ldmatrix.sync.aligned.m8n8.x4.trans.shared.b16 {%0,%1,%2,%3}, [%4];"
                 : "=r"(r0), "=r"(r1), "=r"(r2), "=r"(r3) : "r"(addr));
}
__device__ __forceinline__ void mma16816(float* c, uint32_t a0, uint32_t a1,
                                         uint32_t a2, uint32_t a3,
                                         uint32_t b0, uint32_t b1) {
    asm volatile(
        "mma.sync.aligned.m16n8k16.row.col.f32.bf16.bf16.f32 "
        "{%0,%1,%2,%3}, {%4,%5,%6,%7}, {%8,%9}, {%0,%1,%2,%3};"
        : "+f"(c[0]), "+f"(c[1]), "+f"(c[2]), "+f"(c[3])
        : "r"(a0), "r"(a1), "r"(a2), "r"(a3), "r"(b0), "r"(b1));
}

// ---------------------------------------------------------------------------
// Kernel A: one pass over x -> per-tile channel sums, sa map, and bf16 copy.
// ---------------------------------------------------------------------------
__global__ void __launch_bounds__(256) kA(const float* __restrict__ x,
                                          const float* __restrict__ w1,
                                          const float* __restrict__ b1) {
    __shared__ float sap[8][512];
    __shared__ float csum[256];

    const int tid  = threadIdx.x;
    const int wid  = tid >> 5;
    const int lane = tid & 31;
    const int tile = blockIdx.x;
    const int b    = blockIdx.y;

    const size_t boff = ((size_t)b * CHN) * HW2 + tile * 512;
    const float* xb = x + boff;
    __nv_bfloat16* xo = g_xb + boff;

    float sacc[4][4];
#pragma unroll
    for (int j = 0; j < 4; j++)
#pragma unroll
        for (int jj = 0; jj < 4; jj++) sacc[j][jj] = 0.f;

    const int c0 = wid * 32;
#pragma unroll 4
    for (int ci = 0; ci < 32; ci++) {
        const int c = c0 + ci;
        const float w = __ldg(w1 + c);
        const float* row = xb + (size_t)c * HW2;
        __nv_bfloat16* orow = xo + (size_t)c * HW2;
        float cs = 0.f;
#pragma unroll
        for (int j = 0; j < 4; j++) {
            float4 v = *(const float4*)(row + lane * 4 + j * 128);
            cs += (v.x + v.y) + (v.z + v.w);
            sacc[j][0] = fmaf(v.x, w, sacc[j][0]);
            sacc[j][1] = fmaf(v.y, w, sacc[j][1]);
            sacc[j][2] = fmaf(v.z, w, sacc[j][2]);
            sacc[j][3] = fmaf(v.w, w, sacc[j][3]);
            __nv_bfloat162* o2 = (__nv_bfloat162*)(orow + lane * 4 + j * 128);
            o2[0] = __floats2bfloat162_rn(v.x, v.y);
            o2[1] = __floats2bfloat162_rn(v.z, v.w);
        }
        cs = wred(cs);
        if (lane == 0) csum[c] = cs;
    }

#pragma unroll
    for (int j = 0; j < 4; j++)
#pragma unroll
        for (int jj = 0; jj < 4; jj++)
            sap[wid][lane * 4 + j * 128 + jj] = sacc[j][jj];
    __syncthreads();

    const float b1v = __ldg(b1);
    const int p = tid * 2;
    float v0 = b1v, v1 = b1v;
#pragma unroll
    for (int w = 0; w < 8; w++) { v0 += sap[w][p]; v1 += sap[w][p + 1]; }
    *(float2*)(g_sa + b * HW2 + tile * 512 + p) = make_float2(v0, v1);
    g_xpart[(b * NTILE + tile) * CHN + tid] = csum[tid];
}

// ---------------------------------------------------------------------------
// Kernel W: wr -> bf16 (65536 elems)
// ---------------------------------------------------------------------------
__global__ void __launch_bounds__(256) kW(const float* __restrict__ wr) {
    const int i = (blockIdx.x * 256 + threadIdx.x) * 4;
    float4 v = *(const float4*)(wr + i);
    __nv_bfloat162* o2 = (__nv_bfloat162*)(g_wrb + i);
    o2[0] = __floats2bfloat162_rn(v.x, v.y);
    o2[1] = __floats2bfloat162_rn(v.z, v.w);
}

// ---------------------------------------------------------------------------
// Kernel B: xmean -> g -> ca -> hsig -> LayerNorm
// ---------------------------------------------------------------------------
__global__ void __launch_bounds__(256) kB(const float* __restrict__ w0,
                                          const float* __restrict__ b0,
                                          const float* __restrict__ wb,
                                          const float* __restrict__ bbias,
                                          const float* __restrict__ gamma,
                                          const float* __restrict__ beta) {
    __shared__ float xm[256];
    __shared__ float gg[128];
    __shared__ float cav[256];
    __shared__ float red[16];

    const int b = blockIdx.x;
    const int tid = threadIdx.x;

    {
        float s = 0.f;
        const float* xp = g_xpart + b * NTILE * CHN + tid;
#pragma unroll
        for (int t = 0; t < NTILE; t++) s += xp[t * CHN];
        xm[tid] = s * (1.0f / (float)HW2);
    }
    __syncthreads();

    if (tid < 128) {
        float acc = __ldg(b0 + tid);
        const float* w = w0 + tid * 256;
#pragma unroll 8
        for (int c = 0; c < 256; c++) acc = fmaf(xm[c], __ldg(w + c), acc);
        gg[tid] = acc;
    }
    __syncthreads();

    {
        float acc = __ldg(bbias + tid);
        const float* w = wb + tid * 128;
#pragma unroll 8
        for (int o = 0; o < 128; o++) acc = fmaf(gg[o], __ldg(w + o), acc);
        cav[tid] = hsig(acc);
    }
    __syncthreads();

    const float v = cav[tid];
    float sv = wred(v);
    float sq = wred(v * v);
    if ((tid & 31) == 0) { red[tid >> 5] = sv; red[8 + (tid >> 5)] = sq; }
    __syncthreads();
    float ts = 0.f, tq = 0.f;
#pragma unroll
    for (int i = 0; i < 8; i++) { ts += red[i]; tq += red[8 + i]; }
    const float mu  = ts * (1.0f / 256.0f);
    const float var = tq * (1.0f / 256.0f) - mu * mu;
    const float r   = rsqrtf(var + EPSLN);
    g_ca[b * CHN + tid] = (v - mu) * r * __ldg(gamma + tid) + __ldg(beta + tid);
}

// ---------------------------------------------------------------------------
// Kernel C: ssum[b,c] = sum_p hsig(ca[b,c] * sa[b,p])
// ---------------------------------------------------------------------------
__global__ void __launch_bounds__(256) kC() {
    const int b    = blockIdx.y;
    const int c0   = blockIdx.x * 8;
    const int tid  = threadIdx.x;
    const int wid  = tid >> 5;
    const int lane = tid & 31;

    float cav[8];
#pragma unroll
    for (int i = 0; i < 8; i++) cav[i] = g_ca[b * CHN + c0 + i];

    const float* sap = g_sa + b * HW2;
    float s[8];
#pragma unroll
    for (int i = 0; i < 8; i++) s[i] = 0.f;

    for (int k = 0; k < 64; k++) {
        const float v = sap[tid + k * 256];
#pragma unroll
        for (int i = 0; i < 8; i++) s[i] += hsig(cav[i] * v);
    }

    __shared__ float red[8][8];
#pragma unroll
    for (int i = 0; i < 8; i++) {
        float t = wred(s[i]);
        if (lane == 0) red[wid][i] = t;
    }
    __syncthreads();
    if (tid < 8) {
        float t = 0.f;
#pragma unroll
        for (int w = 0; w < 8; w++) t += red[w][tid];
        g_ssum[b * CHN + c0 + tid] = t;
    }
}

// ---------------------------------------------------------------------------
// Kernel D: bf16 tensor-core GEMM 128x128 (K=256) + fused epilogue.
// out[b,o,p] = hsig(ca[o]*sa[p]) + ssum[o] + br[o] + sum_c wr[o,c]*x[c,p]
// 256 threads = 8 warps (4 in M x 2 in N), warp tile 32x64, mma.m16n8k16.
// ---------------------------------------------------------------------------
__global__ void __launch_bounds__(256, 2) kD(const float* __restrict__ br,
                                             float* __restrict__ out) {
    __shared__ __align__(16) __nv_bfloat16 As[2][128][40];   // [m][k], padded
    __shared__ __align__(16) __nv_bfloat16 Bs[2][32][136];   // [k][n], padded

    const int tid  = threadIdx.x;
    const int lane = tid & 31;
    const int wid  = tid >> 5;
    const int wm   = wid & 3;   // 4 warps in M
    const int wn   = wid >> 2;  // 2 warps in N
    const int bx = blockIdx.x, by = blockIdx.y, b = blockIdx.z;
    const int o0 = by * 128, p0 = bx * 128;

    const __nv_bfloat16* Ag = g_wrb + (size_t)o0 * 256;
    const __nv_bfloat16* Bg = g_xb + ((size_t)b * CHN) * HW2 + p0;

    float acc[2][8][4];
#pragma unroll
    for (int i = 0; i < 2; i++)
#pragma unroll
        for (int j = 0; j < 8; j++)
#pragma unroll
            for (int k = 0; k < 4; k++) acc[i][j][k] = 0.f;

    // per-thread load indices
    const int aRow = tid >> 2, aCol = (tid & 3) * 8;        // A: 2 chunks (rows +0,+64)
    const int bRow = tid >> 4, bCol = (tid & 15) * 8;       // B: 2 chunks (rows +0,+16)

#define LOAD_TILE(s, kt)                                                        \
    {                                                                           \
        cpasync16((uint32_t)__cvta_generic_to_shared(&As[s][aRow][aCol]),       \
                  Ag + (size_t)aRow * 256 + (kt) * 32 + aCol);                  \
        cpasync16((uint32_t)__cvta_generic_to_shared(&As[s][aRow + 64][aCol]),  \
                  Ag + (size_t)(aRow + 64) * 256 + (kt) * 32 + aCol);           \
        cpasync16((uint32_t)__cvta_generic_to_shared(&Bs[s][bRow][bCol]),       \
                  Bg + (size_t)((kt) * 32 + bRow) * HW2 + bCol);                \
        cpasync16((uint32_t)__cvta_generic_to_shared(&Bs[s][bRow + 16][bCol]),  \
                  Bg + (size_t)((kt) * 32 + bRow + 16) * HW2 + bCol);           \
    }

    LOAD_TILE(0, 0);
    asm volatile("cp.async.commit_group;");

    for (int kt = 0; kt < 8; kt++) {
        if (kt < 7) { LOAD_TILE((kt + 1) & 1, kt + 1); }
        asm volatile("cp.async.commit_group;");
        if (kt < 7) asm volatile("cp.async.wait_group 1;");
        else        asm volatile("cp.async.wait_group 0;");
        __syncthreads();

        const int s = kt & 1;
#pragma unroll
        for (int ks = 0; ks < 2; ks++) {
            const int k0 = ks * 16;
            uint32_t bfr[8][2];
#pragma unroll
            for (int j = 0; j < 4; j++) {
                const int n0 = wn * 64 + j * 16;
                uint32_t addr = (uint32_t)__cvta_generic_to_shared(
                    &Bs[s][k0 + (lane & 15)][n0 + 8 * (lane >> 4)]);
                ldsm4t(bfr[2 * j][0], bfr[2 * j][1],
                       bfr[2 * j + 1][0], bfr[2 * j + 1][1], addr);
            }
#pragma unroll
            for (int i = 0; i < 2; i++) {
                const int m0 = wm * 32 + i * 16;
                uint32_t a0, a1, a2, a3;
                uint32_t addr = (uint32_t)__cvta_generic_to_shared(
                    &As[s][m0 + (lane & 15)][k0 + 8 * (lane >> 4)]);
                ldsm4(a0, a1, a2, a3, addr);
#pragma unroll
                for (int j = 0; j < 8; j++)
                    mma16816(acc[i][j], a0, a1, a2, a3, bfr[j][0], bfr[j][1]);
            }
        }
        __syncthreads();
    }
#undef LOAD_TILE

    // ---- fused epilogue ----
    const float* caB = g_ca + b * CHN;
    const float* ssB = g_ssum + b * CHN;
    const float* saB = g_sa + (size_t)b * HW2 + p0;

    float2 sav[8];
#pragma unroll
    for (int j = 0; j < 8; j++) {
        const int p = wn * 64 + j * 8 + 2 * (lane & 3);
        sav[j] = *(const float2*)(saB + p);
    }

#pragma unroll
    for (int i = 0; i < 2; i++) {
#pragma unroll
        for (int h = 0; h < 2; h++) {
            const int o = o0 + wm * 32 + i * 16 + h * 8 + (lane >> 2);
            const float addv = __ldg(br + o) + ssB[o];
            const float cav  = caB[o];
            float* orow = out + ((size_t)b * CHN + o) * HW2 + p0;
#pragma unroll
            for (int j = 0; j < 8; j++) {
                const int p = wn * 64 + j * 8 + 2 * (lane & 3);
                float2 r;
                r.x = acc[i][j][h * 2 + 0] + addv + hsig(cav * sav[j].x);
                r.y = acc[i][j][h * 2 + 1] + addv + hsig(cav * sav[j].y);
                *(float2*)(orow + p) = r;
            }
        }
    }
}

// ---------------------------------------------------------------------------
extern "C" void kernel_launch(void* const* d_in, const int* in_sizes, int n_in,
                              void* d_out, int out_size) {
    const float* x     = (const float*)d_in[0];
    const float* w0    = (const float*)d_in[1];
    const float* b0    = (const float*)d_in[2];
    const float* wb    = (const float*)d_in[3];
    const float* bb    = (const float*)d_in[4];
    const float* w1    = (const float*)d_in[5];
    const float* b1    = (const float*)d_in[6];
    const float* wr    = (const float*)d_in[7];
    const float* br    = (const float*)d_in[8];
    const float* gamma = (const float*)d_in[9];
    const float* beta  = (const float*)d_in[10];
    float* out = (float*)d_out;

    kA<<<dim3(NTILE, BATCH), 256>>>(x, w1, b1);
    kW<<<64, 256>>>(wr);
    kB<<<BATCH, 256>>>(w0, b0, wb, bb, gamma, beta);
    kC<<<dim3(32, BATCH), 256>>>();
    kD<<<dim3(128, 2, BATCH), 256>>>(br, out);
}

// round 4
// speedup vs baseline: 2.7996x; 1.0061x over previous
#include <cuda_runtime.h>
#include <cuda_bf16.h>
#include <cstdint>

#define BATCH 8
#define CHN   256
#define HW2   16384
#define NTILE 32
#define EPSLN 1e-5f

// Scratch (device globals; no allocation allowed)
__device__ float g_xpart[BATCH * NTILE * CHN];
__device__ float g_sa[BATCH * HW2];
__device__ float g_ca[BATCH * CHN];
__device__ float g_ssum[BATCH * CHN];
__device__ __nv_bfloat16 g_xb[(size_t)BATCH * CHN * HW2];   // bf16 copy of x
__device__ __nv_bfloat16 g_wrb[CHN * CHN];                  // bf16 copy of wr

__device__ __forceinline__ float hsig(float v) {
    return __saturatef(fmaf(v, 0.16666667f, 0.5f));
}

__device__ __forceinline__ float wred(float v) {
    v += __shfl_xor_sync(0xffffffffu, v, 16);
    v += __shfl_xor_sync(0xffffffffu, v, 8);
    v += __shfl_xor_sync(0xffffffffu, v, 4);
    v += __shfl_xor_sync(0xffffffffu, v, 2);
    v += __shfl_xor_sync(0xffffffffu, v, 1);
    return v;
}

__device__ __forceinline__ void cpasync16(uint32_t s, const void* g) {
    asm volatile("cp.async.cg.shared.global [%0], [%1], 16;" :: "r"(s), "l"(g));
}
__device__ __forceinline__ void ldsm4(uint32_t& r0, uint32_t& r1, uint32_t& r2,
                                      uint32_t& r3, uint32_t addr) {
    asm volatile("ldmatrix.sync.aligned.m8n8.x4.shared.b16 {%0,%1,%2,%3}, [%4];"
                 : "=r"(r0), "=r"(r1), "=r"(r2), "=r"(r3) : "r"(addr));
}
__device__ __forceinline__ void ldsm4t(uint32_t& r0, uint32_t& r1, uint32_t& r2,
                                       uint32_t& r3, uint32_t addr) {
    asm volatile("ldmatrix.sync.aligned.m8n8.x4.trans.shared.b16 {%0,%1,%2,%3}, [%4];"
                 : "=r"(r0), "=r"(r1), "=r"(r2), "=r"(r3) : "r"(addr));
}
__device__ __forceinline__ void mma16816(float* c, uint32_t a0, uint32_t a1,
                                         uint32_t a2, uint32_t a3,
                                         uint32_t b0, uint32_t b1) {
    asm volatile(
        "mma.sync.aligned.m16n8k16.row.col.f32.bf16.bf16.f32 "
        "{%0,%1,%2,%3}, {%4,%5,%6,%7}, {%8,%9}, {%0,%1,%2,%3};"
        : "+f"(c[0]), "+f"(c[1]), "+f"(c[2]), "+f"(c[3])
        : "r"(a0), "r"(a1), "r"(a2), "r"(a3), "r"(b0), "r"(b1));
}

// ---------------------------------------------------------------------------
// Kernel A: one pass over x -> per-tile channel sums, sa map, and bf16 copy.
// ---------------------------------------------------------------------------
__global__ void __launch_bounds__(256) kA(const float* __restrict__ x,
                                          const float* __restrict__ w1,
                                          const float* __restrict__ b1) {
    __shared__ float sap[8][512];
    __shared__ float csum[256];

    const int tid  = threadIdx.x;
    const int wid  = tid >> 5;
    const int lane = tid & 31;
    const int tile = blockIdx.x;
    const int b    = blockIdx.y;

    const size_t boff = ((size_t)b * CHN) * HW2 + tile * 512;
    const float* xb = x + boff;
    __nv_bfloat16* xo = g_xb + boff;

    float sacc[4][4];
#pragma unroll
    for (int j = 0; j < 4; j++)
#pragma unroll
        for (int jj = 0; jj < 4; jj++) sacc[j][jj] = 0.f;

    const int c0 = wid * 32;
#pragma unroll 4
    for (int ci = 0; ci < 32; ci++) {
        const int c = c0 + ci;
        const float w = __ldg(w1 + c);
        const float* row = xb + (size_t)c * HW2;
        __nv_bfloat16* orow = xo + (size_t)c * HW2;
        float cs = 0.f;
#pragma unroll
        for (int j = 0; j < 4; j++) {
            float4 v = *(const float4*)(row + lane * 4 + j * 128);
            cs += (v.x + v.y) + (v.z + v.w);
            sacc[j][0] = fmaf(v.x, w, sacc[j][0]);
            sacc[j][1] = fmaf(v.y, w, sacc[j][1]);
            sacc[j][2] = fmaf(v.z, w, sacc[j][2]);
            sacc[j][3] = fmaf(v.w, w, sacc[j][3]);
            __nv_bfloat162* o2 = (__nv_bfloat162*)(orow + lane * 4 + j * 128);
            o2[0] = __floats2bfloat162_rn(v.x, v.y);
            o2[1] = __floats2bfloat162_rn(v.z, v.w);
        }
        cs = wred(cs);
        if (lane == 0) csum[c] = cs;
    }

#pragma unroll
    for (int j = 0; j < 4; j++)
#pragma unroll
        for (int jj = 0; jj < 4; jj++)
            sap[wid][lane * 4 + j * 128 + jj] = sacc[j][jj];
    __syncthreads();

    const float b1v = __ldg(b1);
    const int p = tid * 2;
    float v0 = b1v, v1 = b1v;
#pragma unroll
    for (int w = 0; w < 8; w++) { v0 += sap[w][p]; v1 += sap[w][p + 1]; }
    *(float2*)(g_sa + b * HW2 + tile * 512 + p) = make_float2(v0, v1);
    g_xpart[(b * NTILE + tile) * CHN + tid] = csum[tid];
}

// ---------------------------------------------------------------------------
// Kernel W: wr -> bf16 (65536 elems)
// ---------------------------------------------------------------------------
__global__ void __launch_bounds__(256) kW(const float* __restrict__ wr) {
    const int i = (blockIdx.x * 256 + threadIdx.x) * 4;
    float4 v = *(const float4*)(wr + i);
    __nv_bfloat162* o2 = (__nv_bfloat162*)(g_wrb + i);
    o2[0] = __floats2bfloat162_rn(v.x, v.y);
    o2[1] = __floats2bfloat162_rn(v.z, v.w);
}

// ---------------------------------------------------------------------------
// Kernel B: xmean -> g -> ca -> hsig -> LayerNorm
// ---------------------------------------------------------------------------
__global__ void __launch_bounds__(256) kB(const float* __restrict__ w0,
                                          const float* __restrict__ b0,
                                          const float* __restrict__ wb,
                                          const float* __restrict__ bbias,
                                          const float* __restrict__ gamma,
                                          const float* __restrict__ beta) {
    __shared__ float xm[256];
    __shared__ float gg[128];
    __shared__ float cav[256];
    __shared__ float red[16];

    const int b = blockIdx.x;
    const int tid = threadIdx.x;

    {
        float s = 0.f;
        const float* xp = g_xpart + b * NTILE * CHN + tid;
#pragma unroll
        for (int t = 0; t < NTILE; t++) s += xp[t * CHN];
        xm[tid] = s * (1.0f / (float)HW2);
    }
    __syncthreads();

    if (tid < 128) {
        float acc = __ldg(b0 + tid);
        const float* w = w0 + tid * 256;
#pragma unroll 8
        for (int c = 0; c < 256; c++) acc = fmaf(xm[c], __ldg(w + c), acc);
        gg[tid] = acc;
    }
    __syncthreads();

    {
        float acc = __ldg(bbias + tid);
        const float* w = wb + tid * 128;
#pragma unroll 8
        for (int o = 0; o < 128; o++) acc = fmaf(gg[o], __ldg(w + o), acc);
        cav[tid] = hsig(acc);
    }
    __syncthreads();

    const float v = cav[tid];
    float sv = wred(v);
    float sq = wred(v * v);
    if ((tid & 31) == 0) { red[tid >> 5] = sv; red[8 + (tid >> 5)] = sq; }
    __syncthreads();
    float ts = 0.f, tq = 0.f;
#pragma unroll
    for (int i = 0; i < 8; i++) { ts += red[i]; tq += red[8 + i]; }
    const float mu  = ts * (1.0f / 256.0f);
    const float var = tq * (1.0f / 256.0f) - mu * mu;
    const float r   = rsqrtf(var + EPSLN);
    g_ca[b * CHN + tid] = (v - mu) * r * __ldg(gamma + tid) + __ldg(beta + tid);
}

// ---------------------------------------------------------------------------
// Kernel C: ssum[b,c] = sum_p hsig(ca[b,c] * sa[b,p])
// ---------------------------------------------------------------------------
__global__ void __launch_bounds__(256) kC() {
    const int b    = blockIdx.y;
    const int c0   = blockIdx.x * 8;
    const int tid  = threadIdx.x;
    const int wid  = tid >> 5;
    const int lane = tid & 31;

    float cav[8];
#pragma unroll
    for (int i = 0; i < 8; i++) cav[i] = g_ca[b * CHN + c0 + i];

    const float* sap = g_sa + b * HW2;
    float s[8];
#pragma unroll
    for (int i = 0; i < 8; i++) s[i] = 0.f;

    for (int k = 0; k < 64; k++) {
        const float v = sap[tid + k * 256];
#pragma unroll
        for (int i = 0; i < 8; i++) s[i] += hsig(cav[i] * v);
    }

    __shared__ float red[8][8];
#pragma unroll
    for (int i = 0; i < 8; i++) {
        float t = wred(s[i]);
        if (lane == 0) red[wid][i] = t;
    }
    __syncthreads();
    if (tid < 8) {
        float t = 0.f;
#pragma unroll
        for (int w = 0; w < 8; w++) t += red[w][tid];
        g_ssum[b * CHN + c0 + tid] = t;
    }
}

// ---------------------------------------------------------------------------
// Kernel D: bf16 tensor-core GEMM 128x128 (K=256) + fused epilogue.
// out[b,o,p] = hsig(ca[o]*sa[p]) + ssum[o] + br[o] + sum_c wr[o,c]*x[c,p]
// 256 threads = 8 warps (4 in M x 2 in N), warp tile 32x64, mma.m16n8k16.
// ---------------------------------------------------------------------------
__global__ void __launch_bounds__(256, 2) kD(const float* __restrict__ br,
                                             float* __restrict__ out) {
    __shared__ __align__(16) __nv_bfloat16 As[2][128][40];   // [m][k], padded
    __shared__ __align__(16) __nv_bfloat16 Bs[2][32][136];   // [k][n], padded

    const int tid  = threadIdx.x;
    const int lane = tid & 31;
    const int wid  = tid >> 5;
    const int wm   = wid & 3;   // 4 warps in M
    const int wn   = wid >> 2;  // 2 warps in N
    const int bx = blockIdx.x, by = blockIdx.y, b = blockIdx.z;
    const int o0 = by * 128, p0 = bx * 128;

    const __nv_bfloat16* Ag = g_wrb + (size_t)o0 * 256;
    const __nv_bfloat16* Bg = g_xb + ((size_t)b * CHN) * HW2 + p0;

    float acc[2][8][4];
#pragma unroll
    for (int i = 0; i < 2; i++)
#pragma unroll
        for (int j = 0; j < 8; j++)
#pragma unroll
            for (int k = 0; k < 4; k++) acc[i][j][k] = 0.f;

    // per-thread load indices
    const int aRow = tid >> 2, aCol = (tid & 3) * 8;        // A: 2 chunks (rows +0,+64)
    const int bRow = tid >> 4, bCol = (tid & 15) * 8;       // B: 2 chunks (rows +0,+16)

#define LOAD_TILE(s, kt)                                                        \
    {                                                                           \
        cpasync16((uint32_t)__cvta_generic_to_shared(&As[s][aRow][aCol]),       \
                  Ag + (size_t)aRow * 256 + (kt) * 32 + aCol);                  \
        cpasync16((uint32_t)__cvta_generic_to_shared(&As[s][aRow + 64][aCol]),  \
                  Ag + (size_t)(aRow + 64) * 256 + (kt) * 32 + aCol);           \
        cpasync16((uint32_t)__cvta_generic_to_shared(&Bs[s][bRow][bCol]),       \
                  Bg + (size_t)((kt) * 32 + bRow) * HW2 + bCol);                \
        cpasync16((uint32_t)__cvta_generic_to_shared(&Bs[s][bRow + 16][bCol]),  \
                  Bg + (size_t)((kt) * 32 + bRow + 16) * HW2 + bCol);           \
    }

    LOAD_TILE(0, 0);
    asm volatile("cp.async.commit_group;");

    for (int kt = 0; kt < 8; kt++) {
        if (kt < 7) { LOAD_TILE((kt + 1) & 1, kt + 1); }
        asm volatile("cp.async.commit_group;");
        if (kt < 7) asm volatile("cp.async.wait_group 1;");
        else        asm volatile("cp.async.wait_group 0;");
        __syncthreads();

        const int s = kt & 1;
#pragma unroll
        for (int ks = 0; ks < 2; ks++) {
            const int k0 = ks * 16;
            uint32_t bfr[8][2];
#pragma unroll
            for (int j = 0; j < 4; j++) {
                const int n0 = wn * 64 + j * 16;
                uint32_t addr = (uint32_t)__cvta_generic_to_shared(
                    &Bs[s][k0 + (lane & 15)][n0 + 8 * (lane >> 4)]);
                ldsm4t(bfr[2 * j][0], bfr[2 * j][1],
                       bfr[2 * j + 1][0], bfr[2 * j + 1][1], addr);
            }
#pragma unroll
            for (int i = 0; i < 2; i++) {
                const int m0 = wm * 32 + i * 16;
                uint32_t a0, a1, a2, a3;
                uint32_t addr = (uint32_t)__cvta_generic_to_shared(
                    &As[s][m0 + (lane & 15)][k0 + 8 * (lane >> 4)]);
                ldsm4(a0, a1, a2, a3, addr);
#pragma unroll
                for (int j = 0; j < 8; j++)
                    mma16816(acc[i][j], a0, a1, a2, a3, bfr[j][0], bfr[j][1]);
            }
        }
        __syncthreads();
    }
#undef LOAD_TILE

    // ---- fused epilogue ----
    const float* caB = g_ca + b * CHN;
    const float* ssB = g_ssum + b * CHN;
    const float* saB = g_sa + (size_t)b * HW2 + p0;

    float2 sav[8];
#pragma unroll
    for (int j = 0; j < 8; j++) {
        const int p = wn * 64 + j * 8 + 2 * (lane & 3);
        sav[j] = *(const float2*)(saB + p);
    }

#pragma unroll
    for (int i = 0; i < 2; i++) {
#pragma unroll
        for (int h = 0; h < 2; h++) {
            const int o = o0 + wm * 32 + i * 16 + h * 8 + (lane >> 2);
            const float addv = __ldg(br + o) + ssB[o];
            const float cav  = caB[o];
            float* orow = out + ((size_t)b * CHN + o) * HW2 + p0;
#pragma unroll
            for (int j = 0; j < 8; j++) {
                const int p = wn * 64 + j * 8 + 2 * (lane & 3);
                float2 r;
                r.x = acc[i][j][h * 2 + 0] + addv + hsig(cav * sav[j].x);
                r.y = acc[i][j][h * 2 + 1] + addv + hsig(cav * sav[j].y);
                *(float2*)(orow + p) = r;
            }
        }
    }
}

// ---------------------------------------------------------------------------
extern "C" void kernel_launch(void* const* d_in, const int* in_sizes, int n_in,
                              void* d_out, int out_size) {
    const float* x     = (const float*)d_in[0];
    const float* w0    = (const float*)d_in[1];
    const float* b0    = (const float*)d_in[2];
    const float* wb    = (const float*)d_in[3];
    const float* bb    = (const float*)d_in[4];
    const float* w1    = (const float*)d_in[5];
    const float* b1    = (const float*)d_in[6];
    const float* wr    = (const float*)d_in[7];
    const float* br    = (const float*)d_in[8];
    const float* gamma = (const float*)d_in[9];
    const float* beta  = (const float*)d_in[10];
    float* out = (float*)d_out;

    kA<<<dim3(NTILE, BATCH), 256>>>(x, w1, b1);
    kW<<<64, 256>>>(wr);
    kB<<<BATCH, 256>>>(w0, b0, wb, bb, gamma, beta);
    kC<<<dim3(32, BATCH), 256>>>();
    kD<<<dim3(128, 2, BATCH), 256>>>(br, out);
}